// round 2
// baseline (speedup 1.0000x reference)
#include <cuda_runtime.h>
#include <cstdint>

#define N_NODES 100000
#define N_EDGES 1600000
#define HIDDEN  64

// ---------------- scratch (static device globals; no runtime alloc) -------
__device__ __align__(256) float g_agg7[N_NODES * 8];        // [x0,x1,x2,ea0,ea1,ea2,deg,pad]
__device__ __align__(256) float g_h[N_NODES * HIDDEN];      // layer-1 output
__device__ __align__(256) float g_aggh[N_NODES * HIDDEN];   // layer-2 neighbor sum
__device__ __align__(256) int   g_src[N_EDGES];
__device__ __align__(256) int   g_dst[N_EDGES];
__device__ int g_is64;   // 1 if edge_index is int64, 0 if int32

// vectorized global reduction (sm_90+): 1 op instead of 4 scalar atomics
__device__ __forceinline__ void red_add_v4(float* addr, float a, float b, float c, float d) {
    asm volatile(
        "{ .reg .u64 p; cvta.to.global.u64 p, %0;\n"
        "  red.global.add.v4.f32 [p], {%1, %2, %3, %4}; }\n"
        :: "l"(addr), "f"(a), "f"(b), "f"(c), "f"(d) : "memory");
}

// ---------------- K-1: detect edge_index dtype ----------------------------
// int64 values < 100000 => every odd 32-bit word is 0. For int32 data the odd
// words are random node ids; P(all 256 zero) ~ 1e-1280.
__global__ void k_detect(const int* __restrict__ ei32) {
    if (blockIdx.x == 0 && threadIdx.x == 0) {
        int odd_nonzero = 0;
        for (int i = 0; i < 256; i++)
            if (ei32[2 * i + 1] != 0) odd_nonzero++;
        g_is64 = (odd_nonzero == 0) ? 1 : 0;
    }
}

// ---------------- K0: zero accumulators -----------------------------------
__global__ void k_zero() {
    const int stride = gridDim.x * blockDim.x;
    int i = blockIdx.x * blockDim.x + threadIdx.x;
    float4 z = make_float4(0.f, 0.f, 0.f, 0.f);
    for (int t = i; t < (N_NODES * 8) / 4; t += stride)
        reinterpret_cast<float4*>(g_agg7)[t] = z;
    for (int t = i; t < (N_NODES * HIDDEN) / 4; t += stride)
        reinterpret_cast<float4*>(g_aggh)[t] = z;
}

// ---------------- K1: edge pass 1 (aggregate x[src], ea, deg) -------------
__global__ void k_edge1(const float* __restrict__ x,
                        const void* __restrict__ ei,
                        const float* __restrict__ ea) {
    int e = blockIdx.x * blockDim.x + threadIdx.x;
    if (e >= N_EDGES) return;
    int s, d;
    if (g_is64) {
        const long long* p = (const long long*)ei;
        s = (int)p[e];
        d = (int)p[N_EDGES + e];
    } else {
        const int* p = (const int*)ei;
        s = p[e];
        d = p[N_EDGES + e];
    }
    g_src[e] = s;
    g_dst[e] = d;
    float x0 = __ldg(&x[s * 3 + 0]);
    float x1 = __ldg(&x[s * 3 + 1]);
    float x2 = __ldg(&x[s * 3 + 2]);
    float e0 = ea[e * 3 + 0];
    float e1 = ea[e * 3 + 1];
    float e2 = ea[e * 3 + 2];
    float* base = &g_agg7[(size_t)d * 8];
    red_add_v4(base,     x0, x1, x2, e0);
    red_add_v4(base + 4, e1, e2, 1.0f, 0.0f);
}

// ---------------- K2: node pass 1 (6->64 linear + ReLU) -------------------
// thread = (node, j);  h[n][j] = relu( sum_k agg[k]*W1[k][j] + deg*b1[j] )
__global__ void k_node1(const float* __restrict__ W1, const float* __restrict__ b1) {
    int t = blockIdx.x * blockDim.x + threadIdx.x;
    if (t >= N_NODES * HIDDEN) return;
    int n = t >> 6;
    int j = t & 63;
    const float* a = &g_agg7[(size_t)n * 8];
    float acc = a[6] * __ldg(&b1[j]);
    #pragma unroll
    for (int k = 0; k < 6; k++)
        acc += a[k] * __ldg(&W1[k * 64 + j]);
    g_h[t] = fmaxf(acc, 0.0f);
}

// ---------------- K3: edge pass 2 (aggregate h[src]) ----------------------
// 16 threads per edge; each handles one float4 of the 64-wide feature.
__global__ void k_edge2() {
    int t = blockIdx.x * blockDim.x + threadIdx.x;
    int e = t >> 4;
    if (e >= N_EDGES) return;
    int quad = t & 15;
    int s = g_src[e];
    int d = g_dst[e];
    const float4 v = *reinterpret_cast<const float4*>(&g_h[(size_t)s * 64 + quad * 4]);
    red_add_v4(&g_aggh[(size_t)d * 64 + quad * 4], v.x, v.y, v.z, v.w);
}

// ---------------- K4: node pass 2 (67->64 linear + ReLU) + head -----------
// block = 256 threads = 4 nodes x 64 features. agg_h staged in smem.
__global__ void k_node2(const float* __restrict__ W2, const float* __restrict__ b2,
                        const float* __restrict__ W3, const float* __restrict__ b3,
                        float* __restrict__ out) {
    __shared__ float sh[256];
    __shared__ float partial[8];
    int tid = threadIdx.x;
    int base = blockIdx.x * 4;
    int g = tid >> 6;
    int j = tid & 63;
    int n = base + g;

    // cooperative stage of agg_h for the block's 4 nodes (contiguous)
    {
        size_t idx = (size_t)base * 64 + tid;
        sh[tid] = (idx < (size_t)N_NODES * 64) ? g_aggh[idx] : 0.0f;
    }
    __syncthreads();

    float val = 0.0f;
    if (n < N_NODES) {
        const float* a7 = &g_agg7[(size_t)n * 8];
        float acc = a7[6] * __ldg(&b2[j]);
        acc += a7[3] * __ldg(&W2[64 * 64 + j]);
        acc += a7[4] * __ldg(&W2[65 * 64 + j]);
        acc += a7[5] * __ldg(&W2[66 * 64 + j]);
        const float* shn = &sh[g * 64];
        #pragma unroll 16
        for (int i = 0; i < 64; i++)
            acc += shn[i] * __ldg(&W2[i * 64 + j]);
        float h2 = fmaxf(acc, 0.0f);
        val = h2 * __ldg(&W3[j]);
    }

    // reduce 64 lanes (2 warps) per node
    #pragma unroll
    for (int off = 16; off > 0; off >>= 1)
        val += __shfl_down_sync(0xffffffffu, val, off);
    if ((tid & 31) == 0) partial[tid >> 5] = val;
    __syncthreads();
    if (tid < 4) {
        int nn = base + tid;
        if (nn < N_NODES)
            out[nn] = partial[2 * tid] + partial[2 * tid + 1] + __ldg(&b3[0]);
    }
}

// ---------------- launch ---------------------------------------------------
extern "C" void kernel_launch(void* const* d_in, const int* in_sizes, int n_in,
                              void* d_out, int out_size) {
    const float* x   = (const float*)d_in[0];
    const void*  ei  = d_in[1];
    const float* ea  = (const float*)d_in[2];
    const float* W1  = (const float*)d_in[3];
    const float* b1  = (const float*)d_in[4];
    const float* W2  = (const float*)d_in[5];
    const float* b2  = (const float*)d_in[6];
    const float* W3  = (const float*)d_in[7];
    const float* b3  = (const float*)d_in[8];
    float* out = (float*)d_out;

    k_detect<<<1, 32>>>((const int*)ei);
    k_zero<<<1184, 256>>>();
    k_edge1<<<(N_EDGES + 255) / 256, 256>>>(x, ei, ea);
    k_node1<<<(N_NODES * HIDDEN + 255) / 256, 256>>>(W1, b1);
    k_edge2<<<(N_EDGES * 16 + 255) / 256, 256>>>();
    k_node2<<<(N_NODES + 3) / 4, 256>>>(W2, b2, W3, b3, out);
}